// round 1
// baseline (speedup 1.0000x reference)
#include <cuda_runtime.h>
#include <cstdint>
#include <cstddef>

#define BATCH    64
#define SEQ      2048
#define INPUT    8
#define HIDDEN   512
#define NUM_SEEDS 4
#define DD       12
#define OUTK     10
#define ALPHA_F  0.1f
#define JSCALE_F (500.0f/512.0f)

// ---------------- scratch (static __device__ — no allocation) ----------------
__device__ float g_m0[NUM_SEEDS][HIDDEN];
__device__ float g_m1[NUM_SEEDS][HIDDEN];
__device__ float g_n0[NUM_SEEDS][HIDDEN];
__device__ float g_n1[NUM_SEEDS][HIDDEN];
__device__ float g_I [NUM_SEEDS][HIDDEN][INPUT];
__device__ float g_pinv[NUM_SEEDS][OUTK][HIDDEN];
__device__ float g_hid[(size_t)BATCH * SEQ * HIDDEN];   // 256 MB hidden-state scratch

// fast tanh: 1 - 2/(exp(2x)+1). Error ~1e-6; exact at +-inf saturation.
__device__ __forceinline__ float fast_tanh(float x) {
    float e = __expf(2.0f * x);
    return 1.0f - __fdividef(2.0f, e + 1.0f);
}

// ---------------- kernel 1: combined mixture -> m, n, I ----------------
// comb[s,h,d] = sum_e Lc[d,e] * seeds[s,h,e] + mc[d]
// Lc = sum_i w_i * clamp_tril(L_i),  w = clip(mw)/sum
__global__ void setup_kernel(const float* __restrict__ means,
                             const float* __restrict__ L,
                             const float* __restrict__ mw,
                             const float* __restrict__ seeds) {
    __shared__ float Lc[DD][DD];
    __shared__ float mc[DD];
    int tid = threadIdx.x;

    float w0 = fmaxf(mw[0], 1e-6f);
    float w1 = fmaxf(mw[1], 1e-6f);
    float inv = 1.0f / (w0 + w1);
    w0 *= inv; w1 *= inv;

    if (tid < DD * DD) {
        int d = tid / DD, e = tid - d * DD;
        float a = L[d * DD + e];
        float c = L[DD * DD + d * DD + e];
        float v = 0.0f;
        if (e < d) {
            v = w0 * a + w1 * c;
        } else if (e == d) {
            v = w0 * (fabsf(a - 1e-12f) + 1e-12f)
              + w1 * (fabsf(c - 1e-12f) + 1e-12f);
        }
        Lc[d][e] = v;
    }
    if (tid < DD) mc[tid] = w0 * means[tid] + w1 * means[DD + tid];
    __syncthreads();

    int g = blockIdx.x * blockDim.x + tid;      // 0..2047 = s*512 + h
    int s = g >> 9, h = g & 511;

    float sd[DD];
    #pragma unroll
    for (int e = 0; e < DD; e++) sd[e] = seeds[(size_t)g * DD + e];

    float comb[DD];
    #pragma unroll
    for (int d = 0; d < DD; d++) {
        float v = mc[d];
        for (int e = 0; e <= d; e++) v = fmaf(Lc[d][e], sd[e], v);
        comb[d] = v;
    }
    g_m0[s][h] = comb[0];
    g_m1[s][h] = comb[1];
    g_n0[s][h] = comb[2];
    g_n1[s][h] = comb[3];
    #pragma unroll
    for (int i = 0; i < INPUT; i++) g_I[s][h][i] = comb[4 + i];
}

// ---------------- kernel 2: pinv(span) via Gram inverse ----------------
// span = [m | I] (512 x 10) per seed. pinv = (A^T A)^-1 A^T.
__global__ void pinv_kernel() {
    int s = blockIdx.x, tid = threadIdx.x;
    int lane = tid & 31, wid = tid >> 5;

    float a[OUTK];
    a[0] = g_m0[s][tid];
    a[1] = g_m1[s][tid];
    #pragma unroll
    for (int i = 0; i < INPUT; i++) a[2 + i] = g_I[s][tid][i];

    // 55 unique Gram products per thread
    float pr[55];
    {
        int c = 0;
        #pragma unroll
        for (int j = 0; j < OUTK; j++)
            for (int k = j; k < OUTK; k++) pr[c++] = a[j] * a[k];
    }
    // deterministic warp tree reduce
    #pragma unroll
    for (int off = 16; off > 0; off >>= 1)
        for (int c = 0; c < 55; c++)
            pr[c] += __shfl_xor_sync(0xffffffffu, pr[c], off);

    __shared__ float part[16][56];
    if (lane == 0)
        for (int c = 0; c < 55; c++) part[wid][c] = pr[c];
    __syncthreads();

    __shared__ double AG[OUTK][2 * OUTK];   // [G | I] augmented
    if (tid < 55) {
        int c = tid, j = 0, rem = c;
        while (rem >= OUTK - j) { rem -= (OUTK - j); j++; }
        int k = j + rem;
        float v = 0.0f;
        for (int w = 0; w < 16; w++) v += part[w][tid];
        AG[j][k] = (double)v;
        AG[k][j] = (double)v;
    }
    if (tid >= 64 && tid < 64 + OUTK * OUTK) {
        int r = (tid - 64) / OUTK, q = (tid - 64) % OUTK;
        AG[r][OUTK + q] = (r == q) ? 1.0 : 0.0;
    }
    __syncthreads();

    // Gauss-Jordan, SPD so diagonal pivots are safe; double precision.
    for (int p = 0; p < OUTK; p++) {
        if (tid == 0) {
            double ip = 1.0 / AG[p][p];
            for (int q = 0; q < 2 * OUTK; q++) AG[p][q] *= ip;
        }
        __syncthreads();
        if (tid < OUTK && tid != p) {
            double f = AG[tid][p];
            for (int q = 0; q < 2 * OUTK; q++)
                AG[tid][q] = fma(-f, AG[p][q], AG[tid][q]);
        }
        __syncthreads();
    }

    __shared__ float GinvF[OUTK][OUTK];
    if (tid < OUTK * OUTK)
        GinvF[tid / OUTK][tid % OUTK] = (float)AG[tid / OUTK][OUTK + tid % OUTK];
    __syncthreads();

    #pragma unroll
    for (int k = 0; k < OUTK; k++) {
        float v = 0.0f;
        #pragma unroll
        for (int j = 0; j < OUTK; j++) v = fmaf(GinvF[k][j], a[j], v);
        g_pinv[s][k][tid] = v;
    }
}

// ---------------- kernel 3: the sequential RNN scan ----------------
// 1 block per batch, 128 threads, 4 hidden units per thread (contiguous).
// Per step: th=tanh(h); p_r = n_r . th (warp shuffle + smem cross-warp);
// h = 0.9h + 0.1*scale*(m0 p0 + m1 p1) + 0.1*(I x_t); write h to g_hid.
__global__ __launch_bounds__(128, 1) void rnn_kernel(const float* __restrict__ x,
                                                     const int* __restrict__ cur_seeds) {
    const int b = blockIdx.x;
    const int tid = threadIdx.x;
    const int wid = tid >> 5, lane = tid & 31;
    const int s = cur_seeds[b];
    const int h0 = tid * 4;

    const float4 M0 = *(const float4*)&g_m0[s][h0];
    const float4 M1 = *(const float4*)&g_m1[s][h0];
    const float4 N0 = *(const float4*)&g_n0[s][h0];
    const float4 N1 = *(const float4*)&g_n1[s][h0];
    float Iw[4][INPUT];
    #pragma unroll
    for (int c = 0; c < 4; c++) {
        float4 ia = *(const float4*)&g_I[s][h0 + c][0];
        float4 ib = *(const float4*)&g_I[s][h0 + c][4];
        Iw[c][0] = ia.x; Iw[c][1] = ia.y; Iw[c][2] = ia.z; Iw[c][3] = ia.w;
        Iw[c][4] = ib.x; Iw[c][5] = ib.y; Iw[c][6] = ib.z; Iw[c][7] = ib.w;
    }

    const float* xb = x + (size_t)b * SEQ * INPUT;
    float* hb = g_hid + (size_t)b * SEQ * HIDDEN;

    __shared__ __align__(16) float sp[2][2][4];   // [parity][r][warp]

    float h[4] = {0.f, 0.f, 0.f, 0.f};
    float4 xA = *(const float4*)(xb + 0);
    float4 xB = *(const float4*)(xb + 4);

    for (int t = 0; t < SEQ; t++) {
        // prefetch next x row (broadcast loads)
        int tn = (t + 1 < SEQ) ? t + 1 : t;
        float4 xAn = *(const float4*)(xb + (size_t)tn * INPUT);
        float4 xBn = *(const float4*)(xb + (size_t)tn * INPUT + 4);

        float th0 = fast_tanh(h[0]);
        float th1 = fast_tanh(h[1]);
        float th2 = fast_tanh(h[2]);
        float th3 = fast_tanh(h[3]);

        float q0 = fmaf(N0.x, th0, N0.y * th1) + fmaf(N0.z, th2, N0.w * th3);
        float q1 = fmaf(N1.x, th0, N1.y * th1) + fmaf(N1.z, th2, N1.w * th3);

        #pragma unroll
        for (int off = 16; off > 0; off >>= 1) {
            q0 += __shfl_xor_sync(0xffffffffu, q0, off);
            q1 += __shfl_xor_sync(0xffffffffu, q1, off);
        }

        // Ix_t (independent of h — hides under reduction latency)
        float ix[4];
        #pragma unroll
        for (int c = 0; c < 4; c++) {
            float v =          Iw[c][0] * xA.x;
            v = fmaf(Iw[c][1], xA.y, v);
            v = fmaf(Iw[c][2], xA.z, v);
            v = fmaf(Iw[c][3], xA.w, v);
            v = fmaf(Iw[c][4], xB.x, v);
            v = fmaf(Iw[c][5], xB.y, v);
            v = fmaf(Iw[c][6], xB.z, v);
            v = fmaf(Iw[c][7], xB.w, v);
            ix[c] = v;
        }

        int par = t & 1;
        if (lane == 0) { sp[par][0][wid] = q0; sp[par][1][wid] = q1; }
        __syncthreads();
        float4 P0 = *(const float4*)&sp[par][0][0];
        float4 P1 = *(const float4*)&sp[par][1][0];
        float p0 = (P0.x + P0.y) + (P0.z + P0.w);
        float p1 = (P1.x + P1.y) + (P1.z + P1.w);

        const float K1 = ALPHA_F * JSCALE_F;
        h[0] = fmaf(0.9f, h[0], fmaf(K1, fmaf(M0.x, p0, M1.x * p1), ALPHA_F * ix[0]));
        h[1] = fmaf(0.9f, h[1], fmaf(K1, fmaf(M0.y, p0, M1.y * p1), ALPHA_F * ix[1]));
        h[2] = fmaf(0.9f, h[2], fmaf(K1, fmaf(M0.z, p0, M1.z * p1), ALPHA_F * ix[2]));
        h[3] = fmaf(0.9f, h[3], fmaf(K1, fmaf(M0.w, p0, M1.w * p1), ALPHA_F * ix[3]));

        *(float4*)&hb[(size_t)t * HIDDEN + h0] = make_float4(h[0], h[1], h[2], h[3]);

        xA = xAn; xB = xBn;
    }
}

// ---------------- kernel 4: output projection out = pinv_b @ h_t ----------------
// grid (SEQ/32, BATCH), 256 threads = 8 warps, 1 warp per timestep x 4.
__global__ __launch_bounds__(256) void proj_kernel(const int* __restrict__ cur_seeds,
                                                   float* __restrict__ out) {
    const int b = blockIdx.y;
    const int s = cur_seeds[b];
    __shared__ float spv[OUTK][HIDDEN];   // 20 KB
    for (int i = threadIdx.x; i < OUTK * HIDDEN; i += 256)
        (&spv[0][0])[i] = (&g_pinv[s][0][0])[i];
    __syncthreads();

    const int wid = threadIdx.x >> 5, lane = threadIdx.x & 31;
    #pragma unroll 1
    for (int tt = 0; tt < 4; tt++) {
        int t = blockIdx.x * 32 + wid * 4 + tt;
        const float* hr = &g_hid[((size_t)b * SEQ + t) * HIDDEN];
        float acc[OUTK];
        #pragma unroll
        for (int k = 0; k < OUTK; k++) acc[k] = 0.0f;

        #pragma unroll
        for (int q = 0; q < 16; q++) {
            float hv = hr[lane + 32 * q];
            #pragma unroll
            for (int k = 0; k < OUTK; k++)
                acc[k] = fmaf(spv[k][lane + 32 * q], hv, acc[k]);
        }
        #pragma unroll
        for (int off = 16; off > 0; off >>= 1)
            #pragma unroll
            for (int k = 0; k < OUTK; k++)
                acc[k] += __shfl_xor_sync(0xffffffffu, acc[k], off);

        if (lane == 0) {
            float* o = out + ((size_t)b * SEQ + t) * OUTK;
            #pragma unroll
            for (int k = 0; k < OUTK; k++) o[k] = acc[k];
        }
    }
}

// ---------------- launch ----------------
extern "C" void kernel_launch(void* const* d_in, const int* in_sizes, int n_in,
                              void* d_out, int out_size) {
    const float* x     = (const float*)d_in[0];   // (64,2048,8)
    const float* means = (const float*)d_in[1];   // (2,12)
    const float* L     = (const float*)d_in[2];   // (2,12,12)
    const float* mw    = (const float*)d_in[3];   // (2,)
    const float* seeds = (const float*)d_in[4];   // (4,512,12)
    const int*   cs    = (const int*)d_in[5];     // (64,)
    float* out = (float*)d_out;                   // (64,2048,10)

    setup_kernel<<<8, 256>>>(means, L, mw, seeds);
    pinv_kernel<<<NUM_SEEDS, HIDDEN>>>();
    rnn_kernel<<<BATCH, 128>>>(x, cs);
    proj_kernel<<<dim3(SEQ / 32, BATCH), 256>>>(cs, out);
}